// round 5
// baseline (speedup 1.0000x reference)
#include <cuda_runtime.h>
#include <cuda_fp16.h>
#include <cstdint>
#include <cfloat>

#define MAXN 50000
#define MAXE 800000
#define FEAT 64
#define STRIP 8

// ---------------- scratch (no allocations allowed) ----------------
__device__ __half   g_bufh[MAXN * FEAT];  // fp16 messages: dinv * (X @ W)
__device__ float    g_agg[MAXN * FEAT];   // fp32: self-loop init + edge accumulation
__device__ float    g_dinv[MAXN];
__device__ int      g_cnt[MAXN];
__device__ int      g_rowptr[MAXN + 1];
__device__ int2     g_epack[MAXE];        // dst-sorted (src, dst) pairs, int32
__device__ int      g_pos[MAXN];
__device__ unsigned g_gmax[192];          // order-encoded float max per column
__device__ int      g_is32;               // 1 if edge_index is int32

// ---------------- helpers ----------------
__device__ __forceinline__ unsigned long long pack2(float x, float y) {
    unsigned long long u;
    asm("mov.b64 %0, {%1, %2};" : "=l"(u) : "f"(x), "f"(y));
    return u;
}
__device__ __forceinline__ void unpack2(unsigned long long u, float& x, float& y) {
    asm("mov.b64 {%0, %1}, %2;" : "=f"(x), "=f"(y) : "l"(u));
}
__device__ __forceinline__ unsigned long long ffma2(unsigned long long a,
                                                    unsigned long long b,
                                                    unsigned long long c) {
    unsigned long long d;
    asm("fma.rn.f32x2 %0, %1, %2, %3;" : "=l"(d) : "l"(a), "l"(b), "l"(c));
    return d;
}
__device__ __forceinline__ unsigned ford(float f) {
    unsigned u = __float_as_uint(f);
    return (u & 0x80000000u) ? ~u : (u | 0x80000000u);
}
__device__ __forceinline__ float funord(unsigned v) {
    unsigned b = (v & 0x80000000u) ? (v ^ 0x80000000u) : ~v;
    return __uint_as_float(b);
}
__device__ __forceinline__ int edge_at(const void* ei, int E, int which, int e) {
    if (g_is32) return ((const int*)ei)[(size_t)which * E + e];
    return (int)((const long long*)ei)[(size_t)which * E + e];
}
__device__ __forceinline__ void redv4(float* p, float a, float b, float c, float d) {
    asm volatile("red.global.add.v4.f32 [%0], {%1,%2,%3,%4};"
                 :: "l"(p), "f"(a), "f"(b), "f"(c), "f"(d) : "memory");
}
__device__ __forceinline__ void h8_set(float* acc, uint4 u) {
    const __half2* h = (const __half2*)&u;
#pragma unroll
    for (int i = 0; i < 4; i++) {
        float2 f = __half22float2(h[i]);
        acc[2 * i] = f.x; acc[2 * i + 1] = f.y;
    }
}
__device__ __forceinline__ void h8_add(float* acc, uint4 u) {
    const __half2* h = (const __half2*)&u;
#pragma unroll
    for (int i = 0; i < 4; i++) {
        float2 f = __half22float2(h[i]);
        acc[2 * i] += f.x; acc[2 * i + 1] += f.y;
    }
}
// epilogue: scale 16-col accumulator block by dinv, write fp16 msg + fp32 agg
__device__ __forceinline__ void store_row16(int gr, int w, const float* o) {
    uint4 h0, h1;
    __half2* p0 = (__half2*)&h0;
    __half2* p1 = (__half2*)&h1;
#pragma unroll
    for (int i = 0; i < 4; i++) {
        p0[i] = __floats2half2_rn(o[2 * i], o[2 * i + 1]);
        p1[i] = __floats2half2_rn(o[8 + 2 * i], o[9 + 2 * i]);
    }
    *(uint4*)&g_bufh[(size_t)gr * FEAT + w * 16] = h0;
    *(uint4*)&g_bufh[(size_t)gr * FEAT + w * 16 + 8] = h1;
    float4* ap = (float4*)&g_agg[(size_t)gr * FEAT + w * 16];
#pragma unroll
    for (int j = 0; j < 4; j++)
        ap[j] = make_float4(o[4 * j], o[4 * j + 1], o[4 * j + 2], o[4 * j + 3]);
}

// ---------------- preprocessing ----------------
__global__ void init_kernel(int N, int E, const void* ei) {
    int i = blockIdx.x * blockDim.x + threadIdx.x;
    if (i < N) g_cnt[i] = 0;
    if (i < 192) g_gmax[i] = 0u;
    if (i == 0) g_rowptr[N] = E;
    if (blockIdx.x == 0 && threadIdx.x < 32) {
        unsigned long long v = (unsigned long long)((const long long*)ei)[threadIdx.x];
        unsigned m = __ballot_sync(0xffffffffu, (v >> 32) != 0ull);
        if (threadIdx.x == 0) g_is32 = (m != 0u) ? 1 : 0;
    }
}

__global__ void count_kernel(const void* __restrict__ ei, int E) {
    int i = blockIdx.x * blockDim.x + threadIdx.x;
    if (i >= E) return;
    atomicAdd(&g_cnt[edge_at(ei, E, 1, i)], 1);
}

// single-block scan: serial chunk sums + Kogge-Stone over 1024 partials
__global__ __launch_bounds__(1024) void scan_kernel(int N) {
    int t = threadIdx.x;
    int chunk = (N + 1023) / 1024;
    int beg = t * chunk;
    int end = min(beg + chunk, N);
    int s = 0;
    for (int i = beg; i < end; i++) s += g_cnt[i];
    __shared__ int sh[1024];
    sh[t] = s;
    __syncthreads();
    for (int off = 1; off < 1024; off <<= 1) {
        int u = (t >= off) ? sh[t - off] : 0;
        __syncthreads();
        sh[t] += u;
        __syncthreads();
    }
    int run = sh[t] - s;   // exclusive prefix at chunk start
    for (int i = beg; i < end; i++) {
        int c = g_cnt[i];
        g_rowptr[i] = run;
        g_pos[i] = run;
        g_dinv[i] = rsqrtf((float)(c + 1));
        run += c;
    }
}

// dst-sorted packed edges (int32)
__global__ void fill_kernel(const void* __restrict__ ei, int E) {
    int e = blockIdx.x * blockDim.x + threadIdx.x;
    if (e >= E) return;
    int s = edge_at(ei, E, 0, e);
    int d = edge_at(ei, E, 1, e);
    int slot = atomicAdd(&g_pos[d], 1);
    g_epack[slot] = make_int2(s, d);
}

// ---------------- GEMM core (shared by standalone + fused) ----------------
__device__ __forceinline__ void gemm_body(const float* Ws, const float* Xs,
                                          int row0, int nrows, int t) {
    int w = t >> 5;
    int l = t & 31;
    unsigned long long acc0[8], acc1[8];
#pragma unroll
    for (int j = 0; j < 8; j++) { acc0[j] = 0ull; acc1[j] = 0ull; }

#pragma unroll 8
    for (int k = 0; k < 64; k++) {
        float2 xv = *(const float2*)&Xs[k * 66 + 2 * l];
        const float4* wp = (const float4*)&Ws[k * 64 + w * 16];
        float4 wa = wp[0], wb = wp[1], wc = wp[2], wd = wp[3];
        unsigned long long x0 = pack2(xv.x, xv.x);
        unsigned long long x1 = pack2(xv.y, xv.y);
        unsigned long long wq[8] = {
            pack2(wa.x, wa.y), pack2(wa.z, wa.w),
            pack2(wb.x, wb.y), pack2(wb.z, wb.w),
            pack2(wc.x, wc.y), pack2(wc.z, wc.w),
            pack2(wd.x, wd.y), pack2(wd.z, wd.w)};
#pragma unroll
        for (int j = 0; j < 8; j++) {
            acc0[j] = ffma2(x0, wq[j], acc0[j]);
            acc1[j] = ffma2(x1, wq[j], acc1[j]);
        }
    }

#pragma unroll
    for (int rr = 0; rr < 2; rr++) {
        int gr = row0 + 2 * l + rr;
        if (gr >= nrows) continue;
        float dv = g_dinv[gr];
        unsigned long long* acc = rr ? acc1 : acc0;
        float o[16];
#pragma unroll
        for (int j = 0; j < 8; j++) {
            unpack2(acc[j], o[2 * j], o[2 * j + 1]);
            o[2 * j] *= dv; o[2 * j + 1] *= dv;
        }
        store_row16(gr, w, o);
    }
}

// standalone GEMM (layer 1, reads global X)
__global__ __launch_bounds__(128) void gemm_kernel(
    const float* __restrict__ X, int xstride,
    const float* __restrict__ W, int nrows)
{
    __shared__ float Ws[64 * 64];
    __shared__ float Xs[64 * 66];
    int t = threadIdx.x;
    int row0 = blockIdx.x * 64;
    for (int i = t; i < 4096; i += 128) Ws[i] = W[i];
    for (int i = t; i < 4096; i += 128) {
        int r = i >> 6, k = i & 63;
        int gr = row0 + r;
        Xs[k * 66 + r] = (gr < nrows) ? X[(size_t)gr * xstride + k] : 0.f;
    }
    __syncthreads();
    gemm_body(Ws, Xs, row0, nrows, t);
}

// fused: finalize layer L (relu + out write + colmax) feeding GEMM of layer L+1
__global__ __launch_bounds__(128) void fused_fg_kernel(
    const float* __restrict__ bias, float* __restrict__ out, int colbase,
    const float* __restrict__ Wn, int N)
{
    __shared__ float Ws[64 * 64];
    __shared__ float Xs[64 * 66];
    __shared__ float sm[128];
    int t = threadIdx.x;
    int row0 = blockIdx.x * 64;

    for (int i = t; i < 4096; i += 128) Ws[i] = Wn[i];

    int c = t & 63;
    float b = bias[c];
    float mx = -FLT_MAX;
    for (int rr = t >> 6; rr < 64; rr += 2) {
        int gr = row0 + rr;
        float val = 0.f;
        if (gr < N) {
            val = fmaf(g_dinv[gr], g_agg[(size_t)gr * FEAT + c], b);
            val = fmaxf(val, 0.f);                       // fused layers always relu
            out[(size_t)gr * 192 + colbase + c] = val;
            mx = fmaxf(mx, val);
        }
        Xs[c * 66 + rr] = val;                           // transposed, ready for GEMM
    }
    sm[t] = mx;
    __syncthreads();                                     // covers Xs, Ws, sm
    if (t < 64) atomicMax(&g_gmax[colbase + t], ford(fmaxf(sm[t], sm[t + 64])));

    gemm_body(Ws, Xs, row0, N, t);
}

// ---------------- strip-mined segmented scatter (fp16 gather) ----------------
// Thread = (8-edge dst-sorted strip, 8-feature group). 8 independent 16B half
// loads (MLP=8); same-dst runs reduce in fp32 registers; red.f32 at boundaries.
__global__ __launch_bounds__(256) void scatter_kernel(int E) {
    int t = blockIdx.x * 256 + threadIdx.x;
    int grp = t & 7;                  // 8 halves = 16B per group
    int base = (t >> 3) * STRIP;
    if (base >= E) return;

    int2 sd[STRIP];
#pragma unroll
    for (int j = 0; j < STRIP; j++) {
        int e = base + j;
        sd[j] = (e < E) ? g_epack[e] : make_int2(0, -1);
    }
    uint4 v[STRIP];
#pragma unroll
    for (int j = 0; j < STRIP; j++) {
        v[j] = (sd[j].y >= 0)
             ? *(const uint4*)&g_bufh[(size_t)sd[j].x * FEAT + grp * 8]
             : make_uint4(0u, 0u, 0u, 0u);
    }

    float acc[8];
    int curd = sd[0].y;
    h8_set(acc, v[0]);
#pragma unroll
    for (int j = 1; j < STRIP; j++) {
        if (sd[j].y == curd) {
            h8_add(acc, v[j]);
        } else {
            if (curd >= 0) {
                float* p = &g_agg[(size_t)curd * FEAT + grp * 8];
                redv4(p, acc[0], acc[1], acc[2], acc[3]);
                redv4(p + 4, acc[4], acc[5], acc[6], acc[7]);
            }
            curd = sd[j].y;
            h8_set(acc, v[j]);
        }
    }
    if (curd >= 0) {
        float* p = &g_agg[(size_t)curd * FEAT + grp * 8];
        redv4(p, acc[0], acc[1], acc[2], acc[3]);
        redv4(p + 4, acc[4], acc[5], acc[6], acc[7]);
    }
}

// ---------------- standalone finalize (last layer, no relu) ----------------
__global__ __launch_bounds__(256) void finalize_kernel(
    const float* __restrict__ bias, float* __restrict__ out,
    int colbase, int N)
{
    int t = threadIdx.x;
    int c = t & 63, rg = t >> 6;
    float b = bias[c];
    float mx = -FLT_MAX;
    for (int r = blockIdx.x * 4 + rg; r < N; r += gridDim.x * 4) {
        float v = fmaf(g_dinv[r], g_agg[(size_t)r * FEAT + c], b);
        out[(size_t)r * 192 + colbase + c] = v;
        mx = fmaxf(mx, v);
    }
    __shared__ float sm[256];
    sm[t] = mx;
    __syncthreads();
    if (rg == 0) {
        mx = fmaxf(fmaxf(sm[c], sm[64 + c]), fmaxf(sm[128 + c], sm[192 + c]));
        atomicMax(&g_gmax[colbase + c], ford(mx));
    }
}

// ---------------- tail ----------------
__global__ void tail_kernel(float* __restrict__ out,
                            const float* __restrict__ fcW,
                            const float* __restrict__ fcb,
                            const int* __restrict__ tptr, int N)
{
    int t = threadIdx.x;
    if (t < 192) out[(size_t)N * 192 + t] = funord(g_gmax[t]);
    if (t < 4) {
        int tn = *tptr;
        const float* emb = out + (size_t)tn * 192;
        float s = fcb[t];
        for (int k = 0; k < 192; k++) s += emb[k] * fcW[k * 4 + t];
        out[(size_t)N * 192 + 192 + t] = s;
    }
}

// ---------------- launch ----------------
extern "C" void kernel_launch(void* const* d_in, const int* in_sizes, int n_in,
                              void* d_out, int out_size)
{
    const float* x   = (const float*)d_in[0];
    const void*  ei  = d_in[1];
    const int*   tgt = (const int*)d_in[3];
    const float* W1  = (const float*)d_in[4];
    const float* b1  = (const float*)d_in[5];
    const float* W2  = (const float*)d_in[6];
    const float* b2  = (const float*)d_in[7];
    const float* W3  = (const float*)d_in[8];
    const float* b3  = (const float*)d_in[9];
    const float* fcW = (const float*)d_in[10];
    const float* fcb = (const float*)d_in[11];
    float* out = (float*)d_out;

    int N = in_sizes[0] / FEAT;
    int E = in_sizes[1] / 2;

    init_kernel<<<(N + 255) / 256, 256>>>(N, E, ei);
    count_kernel<<<(E + 255) / 256, 256>>>(ei, E);
    scan_kernel<<<1, 1024>>>(N);
    fill_kernel<<<(E + 255) / 256, 256>>>(ei, E);

    int gemm_blocks = (N + 63) / 64;
    int nstrips = (E + STRIP - 1) / STRIP;
    int sc_blocks = (nstrips * 8 + 255) / 256;

    gemm_kernel<<<gemm_blocks, 128>>>(x, FEAT, W1, N);
    scatter_kernel<<<sc_blocks, 256>>>(E);
    fused_fg_kernel<<<gemm_blocks, 128>>>(b1, out, 0, W2, N);
    scatter_kernel<<<sc_blocks, 256>>>(E);
    fused_fg_kernel<<<gemm_blocks, 128>>>(b2, out, 64, W3, N);
    scatter_kernel<<<sc_blocks, 256>>>(E);
    finalize_kernel<<<512, 256>>>(b3, out, 128, N);
    tail_kernel<<<1, 192>>>(out, fcW, fcb, tgt, N);
}